// round 2
// baseline (speedup 1.0000x reference)
#include <cuda_runtime.h>

// ---------------------------------------------------------------------------
// Fused 2-level 3D inverse DWT (db4, mode='zero').
//
// Per level, all three axis synthesis passes are fused in one kernel:
//   smem load (8 bands, 10^3 window) -> x-stage (8->4) -> y-stage (4->2)
//   -> z-stage (2->1) -> global stores of a 14^3 output brick.
//
// Synthesis identity (L=8, conv_transpose stride 2, pad 6):
//   y[2p]   = sum_{t=0..3} x[p+t]*g[6-2t]
//   y[2p+1] = sum_{t=0..3} x[p+t]*g[7-2t]     (no boundary clipping)
// ---------------------------------------------------------------------------

#define G0_0 0.23037781330885523f
#define G0_1 0.7148465705525415f
#define G0_2 0.6308807679295904f
#define G0_3 (-0.02798376941698385f)
#define G0_4 (-0.18703481171888114f)
#define G0_5 0.030841381835986965f
#define G0_6 0.032883011666982945f
#define G0_7 (-0.010597401784997278f)

#define G1_0 (-0.010597401784997278f)
#define G1_1 (-0.032883011666982945f)
#define G1_2 0.030841381835986965f
#define G1_3 0.18703481171888114f
#define G1_4 (-0.02798376941698385f)
#define G1_5 (-0.6308807679295904f)
#define G1_6 0.7148465705525415f
#define G1_7 (-0.23037781330885523f)

__device__ __forceinline__ void sfb_pair(
    float l0, float l1, float l2, float l3,
    float h0, float h1, float h2, float h3,
    float& ye, float& yo)
{
    ye = fmaf(l0, G0_6,
         fmaf(l1, G0_4,
         fmaf(l2, G0_2,
         fmaf(l3, G0_0,
         fmaf(h0, G1_6,
         fmaf(h1, G1_4,
         fmaf(h2, G1_2,
              h3 * G1_0)))))));
    yo = fmaf(l0, G0_7,
         fmaf(l1, G0_5,
         fmaf(l2, G0_3,
         fmaf(l3, G0_1,
         fmaf(h0, G1_7,
         fmaf(h1, G1_5,
         fmaf(h2, G1_3,
              h3 * G1_1)))))));
}

// Level-1 output scratch: 16 x 66^3 floats (18.4 MB)
__device__ float g_LL1[4599936];

// Tile constants: T=7 output pairs per axis, window W=T+3=10, out tile O=14.
#define TT 7
#define WW 10
#define OO 14
#define XPAD 11            // padded x extent of s_in rows (conflict-free)
#define IN_BSTR  (WW*WW*XPAD)       // 1100: per-band stride in s_in
#define B1_ROW   15                 // padded ox extent in buf1
#define B1_BSTR  (WW*WW*B1_ROW)     // 1500: per-band stride in buf1
#define B2_BSTR  (WW*OO*OO)         // 1960: per-band stride in buf2
#define SMEM_FLOATS (8*IN_BSTR + 4*B1_BSTR)   // 8800 + 6000 = 14800
#define TPB 256

// One fused level. lo: low band tensor [16][n^3]; yh: highs [16][7][n^3];
// out: [16][M^3]. ntz = number of z tiles.
__global__ void k_fused_level(const float* __restrict__ lo_t,
                              const float* __restrict__ yh,
                              float* __restrict__ out,
                              int n, int ntz)
{
    extern __shared__ float sm[];
    float* s_in   = sm;                 // [8][10][10][11]
    float* s_buf1 = sm + 8 * IN_BSTR;   // [4][10][10][15]
    float* s_buf2 = sm;                 // alias s_in: [2][10][14][14]

    const int npairs = n - 3;
    const int M = 2 * n - 6;
    const long long vol  = (long long)n * n * n;
    const long long Mvol = (long long)M * M * M;

    const int tid = threadIdx.x;
    const int px0 = blockIdx.x * TT;
    const int py0 = blockIdx.y * TT;
    const int tz  = blockIdx.z % ntz;
    const int slice = blockIdx.z / ntz;
    const int pz0 = tz * TT;

    // ---------------- Stage 0: load 8 bands x 10^3 window ----------------
    {
        const float* lo_slab = lo_t + (long long)slice * vol;
        const float* yh_slab = yh + (long long)slice * 7 * vol;
        #pragma unroll 4
        for (int idx = tid; idx < 8 * WW * WW * WW; idx += TPB) {
            int b = idx / (WW * WW * WW);
            int r = idx - b * (WW * WW * WW);
            int z = r / (WW * WW);
            int r2 = r - z * (WW * WW);
            int y = r2 / WW;
            int x = r2 - y * WW;
            int gz = pz0 + z, gy = py0 + y, gx = px0 + x;
            float v = 0.0f;
            if (gz < n && gy < n && gx < n) {
                const float* src = (b == 0) ? lo_slab
                                            : yh_slab + (long long)(b - 1) * vol;
                v = src[((long long)gz * n + gy) * n + gx];
            }
            s_in[(b * WW + z) * (WW * XPAD) + y * XPAD + x] = v;
        }
    }
    __syncthreads();

    // ---------------- Stage 1: x synthesis, 8 bands -> 4 ----------------
    // rows: j in [0,4), z in [0,10), y in [0,10)  => 400 rows
    for (int idx = tid; idx < 4 * WW * WW; idx += TPB) {
        int j = idx / (WW * WW);
        int r = idx - j * (WW * WW);
        int z = r / WW;
        int y = r - z * WW;
        const float* lp = s_in + ((2 * j) * WW + z) * (WW * XPAD) + y * XPAD;
        const float* hp = lp + IN_BSTR;
        float l[WW], h[WW];
        #pragma unroll
        for (int i = 0; i < WW; i++) { l[i] = lp[i]; h[i] = hp[i]; }
        float* op = s_buf1 + (j * WW + z) * (WW * B1_ROW) + y * B1_ROW;
        #pragma unroll
        for (int p = 0; p < TT; p++) {
            float ye, yo;
            sfb_pair(l[p], l[p+1], l[p+2], l[p+3],
                     h[p], h[p+1], h[p+2], h[p+3], ye, yo);
            op[2 * p]     = ye;
            op[2 * p + 1] = yo;
        }
    }
    __syncthreads();

    // ---------------- Stage 2: y synthesis, 4 bands -> 2 ----------------
    // cols: j in [0,2), z in [0,10), ox in [0,14) => 280 cols
    for (int idx = tid; idx < 2 * WW * OO; idx += TPB) {
        int j = idx / (WW * OO);
        int r = idx - j * (WW * OO);
        int z = r / OO;
        int ox = r - z * OO;
        const float* lp = s_buf1 + ((2 * j) * WW + z) * (WW * B1_ROW) + ox;
        const float* hp = lp + B1_BSTR;
        float l[WW], h[WW];
        #pragma unroll
        for (int i = 0; i < WW; i++) { l[i] = lp[i * B1_ROW]; h[i] = hp[i * B1_ROW]; }
        float* op = s_buf2 + (j * WW + z) * (OO * OO) + ox;
        #pragma unroll
        for (int p = 0; p < TT; p++) {
            float ye, yo;
            sfb_pair(l[p], l[p+1], l[p+2], l[p+3],
                     h[p], h[p+1], h[p+2], h[p+3], ye, yo);
            op[(2 * p) * OO]     = ye;
            op[(2 * p + 1) * OO] = yo;
        }
    }
    __syncthreads();

    // ---------------- Stage 3: z synthesis, 2 bands -> out ----------------
    // cols: oy in [0,14), ox in [0,14) => 196 cols
    if (tid < OO * OO) {
        int oy = tid / OO;
        int ox = tid - oy * OO;
        const float* lp = s_buf2 + oy * OO + ox;
        const float* hp = lp + B2_BSTR;
        float l[WW], h[WW];
        #pragma unroll
        for (int i = 0; i < WW; i++) { l[i] = lp[i * OO * OO]; h[i] = hp[i * OO * OO]; }

        int gyc = 2 * py0 + oy;
        int gxc = 2 * px0 + ox;
        if (gyc < M && gxc < M) {
            float* oslab = out + (long long)slice * Mvol;
            #pragma unroll
            for (int p = 0; p < TT; p++) {
                float ye, yo;
                sfb_pair(l[p], l[p+1], l[p+2], l[p+3],
                         h[p], h[p+1], h[p+2], h[p+3], ye, yo);
                int oz = 2 * (pz0 + p);
                if (oz < M) {
                    long long ob = ((long long)oz * M + gyc) * M + gxc;
                    oslab[ob]               = ye;
                    oslab[ob + (long long)M * M] = yo;
                }
            }
        }
    }
}

extern "C" void kernel_launch(void* const* d_in, const int* in_sizes, int n_in,
                              void* d_out, int out_size)
{
    (void)in_sizes; (void)n_in; (void)out_size;

    const float* yl  = (const float*)d_in[0];  // (2,8,36,36,36)   -> 16 slices
    const float* yh0 = (const float*)d_in[1];  // (2,8,7,66,66,66)
    const float* yh1 = (const float*)d_in[2];  // (2,8,7,36,36,36)
    float* out = (float*)d_out;                // (2,8,126,126,126)

    float* LL1;
    cudaGetSymbolAddress((void**)&LL1, g_LL1);

    const size_t smem_bytes = SMEM_FLOATS * sizeof(float);  // 59.2 KB
    cudaFuncSetAttribute(k_fused_level,
                         cudaFuncAttributeMaxDynamicSharedMemorySize,
                         (int)smem_bytes);

    // Level 1: n=36 -> M=66. npairs=33 -> 5 tiles/axis.
    {
        const int n = 36;
        const int nt = (n - 3 + TT - 1) / TT;   // 5
        dim3 grid(nt, nt, nt * 16);
        k_fused_level<<<grid, TPB, smem_bytes>>>(yl, yh1, LL1, n, nt);
    }

    // Level 2: n=66 -> M=126. npairs=63 -> 9 tiles/axis.
    {
        const int n = 66;
        const int nt = (n - 3 + TT - 1) / TT;   // 9
        dim3 grid(nt, nt, nt * 16);
        k_fused_level<<<grid, TPB, smem_bytes>>>(LL1, yh0, out, n, nt);
    }
}

// round 3
// speedup vs baseline: 1.9011x; 1.9011x over previous
#include <cuda_runtime.h>

// ---------------------------------------------------------------------------
// 2-level 3D inverse DWT (db4, mode='zero'), axis-reordered (z, then y+x fused).
//
// Synthesis identity (L=8, conv_transpose stride 2, pad 6): out len M = 2n-6,
//   y[2p]   = sum_{t=0..3} x[p+t]*g[6-2t]
//   y[2p+1] = sum_{t=0..3} x[p+t]*g[7-2t]      (no boundary clipping)
//
// Band index b = 4*zbit + 2*ybit + xbit (b=0 is the low band; b>=1 -> yh[b-1]).
// z-pass pairs (b, b+4); y-pass pairs (b2, b2+2); x-pass pairs (0,1).
// ---------------------------------------------------------------------------

#define G0_0 0.23037781330885523f
#define G0_1 0.7148465705525415f
#define G0_2 0.6308807679295904f
#define G0_3 (-0.02798376941698385f)
#define G0_4 (-0.18703481171888114f)
#define G0_5 0.030841381835986965f
#define G0_6 0.032883011666982945f
#define G0_7 (-0.010597401784997278f)

#define G1_0 (-0.010597401784997278f)
#define G1_1 (-0.032883011666982945f)
#define G1_2 0.030841381835986965f
#define G1_3 0.18703481171888114f
#define G1_4 (-0.02798376941698385f)
#define G1_5 (-0.6308807679295904f)
#define G1_6 0.7148465705525415f
#define G1_7 (-0.23037781330885523f)

__device__ __forceinline__ void sfb_pair(
    float l0, float l1, float l2, float l3,
    float h0, float h1, float h2, float h3,
    float& ye, float& yo)
{
    ye = fmaf(l0, G0_6,
         fmaf(l1, G0_4,
         fmaf(l2, G0_2,
         fmaf(l3, G0_0,
         fmaf(h0, G1_6,
         fmaf(h1, G1_4,
         fmaf(h2, G1_2,
              h3 * G1_0)))))));
    yo = fmaf(l0, G0_7,
         fmaf(l1, G0_5,
         fmaf(l2, G0_3,
         fmaf(l3, G0_1,
         fmaf(h0, G1_7,
         fmaf(h1, G1_5,
         fmaf(h2, G1_3,
              h3 * G1_1)))))));
}

// Scratch: z-pass output, level-2 max: 16 slices * 4 bands * 126 * 66*66
__device__ float g_mid[35126784];   // 140.5 MB
__device__ float g_LL1[4599936];    // 16 * 66^3 (18.4 MB)

// ---------------------------------------------------------------------------
// Kernel 1: z synthesis, streaming lines. 8 bands -> 4.
// Thread = (slice, b4, inner i over n^2). Rolling 4-reg window along z.
// Output layout: [slice][b4][M_z][n^2].
// ---------------------------------------------------------------------------
__global__ void k_zpass(const float* __restrict__ lo_t,
                        const float* __restrict__ yh,
                        float* __restrict__ out, int n)
{
    const int n2 = n * n;
    const int M = 2 * n - 6;
    int i = blockIdx.x * blockDim.x + threadIdx.x;
    if (i >= n2) return;

    const int g = blockIdx.y;        // slice*4 + b4
    const int slice = g >> 2;
    const int b4 = g & 3;
    const long long vol = (long long)n2 * n;

    const float* lo = (b4 == 0) ? lo_t + (long long)slice * vol
                                : yh + ((long long)slice * 7 + (b4 - 1)) * vol;
    const float* hi = yh + ((long long)slice * 7 + (b4 + 3)) * vol;
    lo += i; hi += i;

    float l0 = lo[0], l1 = lo[n2], l2 = lo[2 * n2];
    float h0 = hi[0], h1 = hi[n2], h2 = hi[2 * n2];
    const float* lp = lo + 3LL * n2;
    const float* hp = hi + 3LL * n2;
    float* op = out + ((long long)g * M) * n2 + i;

    const int np = n - 3;
    #pragma unroll 3
    for (int p = 0; p < np; p++) {
        float l3 = *lp, h3 = *hp;
        float ye, yo;
        sfb_pair(l0, l1, l2, l3, h0, h1, h2, h3, ye, yo);
        op[0]  = ye;
        op[n2] = yo;
        l0 = l1; l1 = l2; l2 = l3;
        h0 = h1; h1 = h2; h2 = h3;
        lp += n2; hp += n2; op += 2LL * n2;
    }
}

// ---------------------------------------------------------------------------
// Kernel 2: fused y + x synthesis. 4 bands -> 1.
// Block = (y-tile, oz, slice). smem: 4 bands x 10 rows x n, then 2 x 14 x n.
// ---------------------------------------------------------------------------
#define TY 7
#define WIN 10
#define K2_TPB 128

__global__ void k_yx(const float* __restrict__ in,
                     float* __restrict__ out, int n)
{
    extern __shared__ float sm[];
    const int n2 = n * n;
    const int M = 2 * n - 6;
    const int npx = n - 3;

    float* s_in  = sm;                // [4][WIN][n]
    float* s_mid = sm + 4 * WIN * n;  // [2][2*TY][n]

    const int tid   = threadIdx.x;
    const int slice = blockIdx.z;
    const int oz    = blockIdx.y;
    const int py0   = blockIdx.x * TY;

    // ---- load 4 bands x WIN y-rows x n (coalesced rows) ----
    const float* base = in + ((long long)(slice * 4) * M + oz) * n2;
    const int nload = 4 * WIN * n;
    for (int idx = tid; idx < nload; idx += K2_TPB) {
        int b  = idx / (WIN * n);
        int r  = idx - b * (WIN * n);
        int iy = r / n;
        int x  = r - iy * n;
        int gy = py0 + iy;
        float v = 0.0f;
        if (gy < n) v = base[(long long)b * M * n2 + gy * n + x];
        s_in[idx] = v;
    }
    __syncthreads();

    // ---- y synthesis: bands (j, j+2) -> s_mid[j], j in {0,1} ----
    for (int idx = tid; idx < 2 * n; idx += K2_TPB) {
        int j = idx / n;
        int x = idx - j * n;
        const float* lp = s_in + j * WIN * n + x;
        const float* hp = s_in + (j + 2) * WIN * n + x;
        float l[WIN], h[WIN];
        #pragma unroll
        for (int k = 0; k < WIN; k++) { l[k] = lp[k * n]; h[k] = hp[k * n]; }
        float* op = s_mid + j * (2 * TY) * n + x;
        #pragma unroll
        for (int p = 0; p < TY; p++) {
            float ye, yo;
            sfb_pair(l[p], l[p+1], l[p+2], l[p+3],
                     h[p], h[p+1], h[p+2], h[p+3], ye, yo);
            op[(2 * p) * n]     = ye;
            op[(2 * p + 1) * n] = yo;
        }
    }
    __syncthreads();

    // ---- x synthesis: 14 rows, straight to global ----
    const long long Mvol = (long long)M * M * M;
    float* oslab = out + (long long)slice * Mvol + ((long long)oz * M) * M;
    const int items = 2 * TY * npx;
    for (int idx = tid; idx < items; idx += K2_TPB) {
        int row = idx / npx;
        int p   = idx - row * npx;
        int oy  = 2 * py0 + row;
        if (oy >= M) continue;
        const float* lp = s_mid + row * n + p;
        const float* hp = lp + (2 * TY) * n;
        float ye, yo;
        sfb_pair(lp[0], lp[1], lp[2], lp[3],
                 hp[0], hp[1], hp[2], hp[3], ye, yo);
        float* o = oslab + (long long)oy * M + 2 * p;
        o[0] = ye;
        o[1] = yo;
    }
}

extern "C" void kernel_launch(void* const* d_in, const int* in_sizes, int n_in,
                              void* d_out, int out_size)
{
    (void)in_sizes; (void)n_in; (void)out_size;

    const float* yl  = (const float*)d_in[0];  // (2,8,36,36,36)   16 slices
    const float* yh0 = (const float*)d_in[1];  // (2,8,7,66,66,66)
    const float* yh1 = (const float*)d_in[2];  // (2,8,7,36,36,36)
    float* out = (float*)d_out;                // (2,8,126,126,126)

    float *MID, *LL1;
    cudaGetSymbolAddress((void**)&MID, g_mid);
    cudaGetSymbolAddress((void**)&LL1, g_LL1);

    // ---------------- Level 1: n=36 -> 66 ----------------
    {
        const int n = 36, n2 = n * n, M = 2 * n - 6;
        dim3 gz((n2 + 255) / 256, 64);
        k_zpass<<<gz, 256>>>(yl, yh1, MID, n);

        const int nyt = (n - 3 + TY - 1) / TY;   // 5
        dim3 gyx(nyt, M, 16);
        size_t sh = (size_t)(4 * WIN * n + 2 * (2 * TY) * n) * sizeof(float);
        k_yx<<<gyx, K2_TPB, sh>>>(MID, LL1, n);
    }

    // ---------------- Level 2: n=66 -> 126 ----------------
    {
        const int n = 66, n2 = n * n, M = 2 * n - 6;
        dim3 gz((n2 + 255) / 256, 64);
        k_zpass<<<gz, 256>>>(LL1, yh0, MID, n);

        const int nyt = (n - 3 + TY - 1) / TY;   // 9
        dim3 gyx(nyt, M, 16);
        size_t sh = (size_t)(4 * WIN * n + 2 * (2 * TY) * n) * sizeof(float);
        k_yx<<<gyx, K2_TPB, sh>>>(MID, out, n);
    }
}

// round 4
// speedup vs baseline: 3.0189x; 1.5880x over previous
#include <cuda_runtime.h>

// ---------------------------------------------------------------------------
// 2-level 3D inverse DWT (db4, mode='zero'), axis-reordered (z, then y+x fused).
// Templated on N (compile-time index math), float2-vectorized.
//
// Synthesis identity (L=8, conv_transpose stride 2, pad 6): out len M = 2n-6,
//   y[2p]   = sum_{t=0..3} x[p+t]*g[6-2t]
//   y[2p+1] = sum_{t=0..3} x[p+t]*g[7-2t]      (no boundary clipping)
//
// Band b = 4*zbit + 2*ybit + xbit; b=0 low (yl/LL1), b>=1 -> yh[b-1].
// z-pass pairs (b4, b4+4); y-pass pairs (j, j+2); x-pass pairs (0,1).
// ---------------------------------------------------------------------------

#define G0_0 0.23037781330885523f
#define G0_1 0.7148465705525415f
#define G0_2 0.6308807679295904f
#define G0_3 (-0.02798376941698385f)
#define G0_4 (-0.18703481171888114f)
#define G0_5 0.030841381835986965f
#define G0_6 0.032883011666982945f
#define G0_7 (-0.010597401784997278f)

#define G1_0 (-0.010597401784997278f)
#define G1_1 (-0.032883011666982945f)
#define G1_2 0.030841381835986965f
#define G1_3 0.18703481171888114f
#define G1_4 (-0.02798376941698385f)
#define G1_5 (-0.6308807679295904f)
#define G1_6 0.7148465705525415f
#define G1_7 (-0.23037781330885523f)

__device__ __forceinline__ void sfb_pair(
    float l0, float l1, float l2, float l3,
    float h0, float h1, float h2, float h3,
    float& ye, float& yo)
{
    ye = fmaf(l0, G0_6,
         fmaf(l1, G0_4,
         fmaf(l2, G0_2,
         fmaf(l3, G0_0,
         fmaf(h0, G1_6,
         fmaf(h1, G1_4,
         fmaf(h2, G1_2,
              h3 * G1_0)))))));
    yo = fmaf(l0, G0_7,
         fmaf(l1, G0_5,
         fmaf(l2, G0_3,
         fmaf(l3, G0_1,
         fmaf(h0, G1_7,
         fmaf(h1, G1_5,
         fmaf(h2, G1_3,
              h3 * G1_1)))))));
}

__device__ __forceinline__ void sfb_pair2(
    float2 l0, float2 l1, float2 l2, float2 l3,
    float2 h0, float2 h1, float2 h2, float2 h3,
    float2& ye, float2& yo)
{
    sfb_pair(l0.x, l1.x, l2.x, l3.x, h0.x, h1.x, h2.x, h3.x, ye.x, yo.x);
    sfb_pair(l0.y, l1.y, l2.y, l3.y, h0.y, h1.y, h2.y, h3.y, ye.y, yo.y);
}

// Scratch: z-pass output, level-2 max: 16 slices * 4 bands * 126 * 66*66
__device__ float g_mid[35126784];   // 140.5 MB
__device__ float g_LL1[4599936];    // 16 * 66^3 (18.4 MB)

// ---------------------------------------------------------------------------
// Kernel 1: z synthesis, streaming lines, float2 over the inner (y*x) index.
// 8 bands -> 4. Output layout: [slice][b4][M_z][N^2].
// ---------------------------------------------------------------------------
template<int N>
__global__ void k_zpass(const float* __restrict__ lo_t,
                        const float* __restrict__ yh,
                        float* __restrict__ out)
{
    constexpr int N2 = N * N;
    constexpr int M  = 2 * N - 6;
    constexpr int S  = N2 / 2;           // float2 stride along z
    constexpr long long VOL = (long long)N2 * N;

    int i2 = (blockIdx.x * blockDim.x + threadIdx.x);
    if (i2 >= S) return;

    const int g = blockIdx.y;            // slice*4 + b4
    const int slice = g >> 2;
    const int b4 = g & 3;

    const float* lo_s = (b4 == 0) ? lo_t + (long long)slice * VOL
                                  : yh + ((long long)slice * 7 + (b4 - 1)) * VOL;
    const float* hi_s = yh + ((long long)slice * 7 + (b4 + 3)) * VOL;

    const float2* lp = (const float2*)lo_s + i2;
    const float2* hp = (const float2*)hi_s + i2;
    float2* op = (float2*)(out + (long long)g * M * N2) + i2;

    float2 l0 = lp[0], l1 = lp[S], l2 = lp[2 * S];
    float2 h0 = hp[0], h1 = hp[S], h2 = hp[2 * S];
    lp += 3 * S; hp += 3 * S;

    #pragma unroll 3
    for (int p = 0; p < N - 3; p++) {
        float2 l3 = *lp, h3 = *hp;
        float2 ye, yo;
        sfb_pair2(l0, l1, l2, l3, h0, h1, h2, h3, ye, yo);
        op[0] = ye;
        op[S] = yo;
        l0 = l1; l1 = l2; l2 = l3;
        h0 = h1; h1 = h2; h2 = h3;
        lp += S; hp += S; op += 2 * S;
    }
}

// ---------------------------------------------------------------------------
// Kernel 2: fused y + x synthesis. 4 bands -> 1.
// Block = (y-tile of 7 pairs, oz, slice). smem: [4][10][N] in, [2][14][N] mid.
// ---------------------------------------------------------------------------
#define TY 7
#define WIN 10
#define K2_TPB 256

template<int N>
__global__ void k_yx(const float* __restrict__ in,
                     float* __restrict__ out)
{
    constexpr int N2  = N * N;
    constexpr int M   = 2 * N - 6;
    constexpr int NPX = N - 3;
    constexpr int NH  = N / 2;

    extern __shared__ float sm[];
    float* s_in  = sm;                 // [4][WIN][N]
    float* s_mid = sm + 4 * WIN * N;   // [2][2*TY][N]

    const int tid   = threadIdx.x;
    const int slice = blockIdx.z;
    const int oz    = blockIdx.y;
    const int py0   = blockIdx.x * TY;

    // ---- load 4 bands x WIN y-rows x N floats (float2, coalesced rows) ----
    const float* base = in + ((long long)(slice * 4) * M + oz) * N2;
    constexpr int NLOAD = 4 * WIN * NH;
    #pragma unroll 2
    for (int idx = tid; idx < NLOAD; idx += K2_TPB) {
        int b  = idx / (WIN * NH);
        int r  = idx - b * (WIN * NH);
        int iy = r / NH;
        int x2 = r - iy * NH;
        int gy = py0 + iy;
        float2 v = make_float2(0.0f, 0.0f);
        if (gy < N)
            v = *(const float2*)(base + (long long)b * M * N2 + gy * N + 2 * x2);
        *(float2*)(s_in + (b * WIN + iy) * N + 2 * x2) = v;
    }
    __syncthreads();

    // ---- y synthesis: bands (j, j+2) -> s_mid[j]; item = (j, p, x2) ----
    constexpr int YITEMS = 2 * TY * NH;
    #pragma unroll 2
    for (int idx = tid; idx < YITEMS; idx += K2_TPB) {
        int j  = idx / (TY * NH);
        int r  = idx - j * (TY * NH);
        int p  = r / NH;
        int x2 = r - p * NH;
        const float* lp = s_in + (j * WIN + p) * N + 2 * x2;
        const float* hp = lp + 2 * WIN * N;
        float2 l0 = *(const float2*)(lp);
        float2 l1 = *(const float2*)(lp + N);
        float2 l2 = *(const float2*)(lp + 2 * N);
        float2 l3 = *(const float2*)(lp + 3 * N);
        float2 h0 = *(const float2*)(hp);
        float2 h1 = *(const float2*)(hp + N);
        float2 h2 = *(const float2*)(hp + 2 * N);
        float2 h3 = *(const float2*)(hp + 3 * N);
        float2 ye, yo;
        sfb_pair2(l0, l1, l2, l3, h0, h1, h2, h3, ye, yo);
        float* op = s_mid + (j * 2 * TY + 2 * p) * N + 2 * x2;
        *(float2*)op       = ye;
        *(float2*)(op + N) = yo;
    }
    __syncthreads();

    // ---- x synthesis: item = (row, p), float2 store to global ----
    constexpr long long MVOL = (long long)M * M * M;
    float* oslab = out + (long long)slice * MVOL + ((long long)oz * M) * M;
    constexpr int XITEMS = 2 * TY * NPX;
    #pragma unroll 2
    for (int idx = tid; idx < XITEMS; idx += K2_TPB) {
        int row = idx / NPX;
        int p   = idx - row * NPX;
        int oy  = 2 * py0 + row;
        if (oy >= M) continue;
        const float* lp = s_mid + row * N + p;
        const float* hp = lp + 2 * TY * N;
        float ye, yo;
        sfb_pair(lp[0], lp[1], lp[2], lp[3],
                 hp[0], hp[1], hp[2], hp[3], ye, yo);
        *(float2*)(oslab + (long long)oy * M + 2 * p) = make_float2(ye, yo);
    }
}

extern "C" void kernel_launch(void* const* d_in, const int* in_sizes, int n_in,
                              void* d_out, int out_size)
{
    (void)in_sizes; (void)n_in; (void)out_size;

    const float* yl  = (const float*)d_in[0];  // (2,8,36,36,36)   16 slices
    const float* yh0 = (const float*)d_in[1];  // (2,8,7,66,66,66)
    const float* yh1 = (const float*)d_in[2];  // (2,8,7,36,36,36)
    float* out = (float*)d_out;                // (2,8,126,126,126)

    float *MID, *LL1;
    cudaGetSymbolAddress((void**)&MID, g_mid);
    cudaGetSymbolAddress((void**)&LL1, g_LL1);

    // ---------------- Level 1: n=36 -> 66 ----------------
    {
        constexpr int N = 36, M = 2 * N - 6;
        dim3 gz((N * N / 2 + 255) / 256, 64);
        k_zpass<N><<<gz, 256>>>(yl, yh1, MID);

        constexpr int NYT = (N - 3 + TY - 1) / TY;   // 5
        dim3 gyx(NYT, M, 16);
        size_t sh = (size_t)(4 * WIN * N + 2 * (2 * TY) * N) * sizeof(float);
        k_yx<N><<<gyx, K2_TPB, sh>>>(MID, LL1);
    }

    // ---------------- Level 2: n=66 -> 126 ----------------
    {
        constexpr int N = 66, M = 2 * N - 6;
        dim3 gz((N * N / 2 + 255) / 256, 64);
        k_zpass<N><<<gz, 256>>>(LL1, yh0, MID);

        constexpr int NYT = (N - 3 + TY - 1) / TY;   // 9
        dim3 gyx(NYT, M, 16);
        size_t sh = (size_t)(4 * WIN * N + 2 * (2 * TY) * N) * sizeof(float);
        k_yx<N><<<gyx, K2_TPB, sh>>>(MID, out);
    }
}